// round 8
// baseline (speedup 1.0000x reference)
#include <cuda_runtime.h>
#include <cuda_fp16.h>
#include <cstdint>

// out[M,1024] = merged[M,4096] @ W[4096,1024], fp32 via single-pass fp16 HMMA.
// merged row m = concat of 4 gathered rows of image_features (2x2 patch merge).
// R8: CTA tile 128x256, warp tile 64x64 (8 warps) -> 33% less LDSM traffic per
// MAC (shared crossbar was co-binding at 128x128 / 64x32). 4-stage pipeline.

#define PATCH 14
#define HID   1024
#define KTOT  4096
#define MPAD  15104

#define BM 128
#define BN 256
#define BK 64                       // 64 halves = 128 B row: natural swizzle atom
#define NCHUNK (KTOT / BK)          // 64
#define TILE_A (128 * 128)          // 16384 B
#define TILE_B (256 * 128)          // 32768 B
#define STAGE_B (TILE_A + TILE_B)   // 49152
#define NSTAGE 4
#define SMEM_TOTAL (NSTAGE * STAGE_B)   // 196608 (1 CTA/SM)

// scratch (static device memory — no runtime allocation)
__device__ __align__(128) __half g_Ah[(size_t)MPAD * KTOT];
__device__ __align__(128) __half g_Bh[(size_t)HID * KTOT];

// ─── prep: gather + fp32 -> fp16 into merged [M,4096] layout ────────────────
__global__ void convert_A_kernel(const float* __restrict__ feat,
                                 const int* __restrict__ sizes, int n_images) {
    __shared__ int s_src[4];
    const int m = blockIdx.x;
    const int tid = threadIdx.x;
    if (tid < 4) {
        int toff = 0, moff = 0, src = 0;
        for (int i = 0; i < n_images; i++) {
            const int h = sizes[2 * i] / PATCH, w = sizes[2 * i + 1] / PATCH;
            const int w2 = w >> 1, mr = (h >> 1) * w2;
            if (m < moff + mr) {
                const int r = m - moff;
                const int gr = r / w2, gc = r - gr * w2;
                src = toff + (2 * gr + (tid >> 1)) * w + 2 * gc + (tid & 1);
                break;
            }
            toff += h * w; moff += mr;
        }
        s_src[tid] = src;
    }
    __syncthreads();
    const int ki = tid >> 6;
    const int c  = (tid & 63) * 16;
    const float4* src = (const float4*)(feat + (size_t)s_src[ki] * HID + c);
    const float4 x0 = src[0], x1 = src[1], x2 = src[2], x3 = src[3];
    __half2 h[8];
    h[0] = __floats2half2_rn(x0.x, x0.y); h[1] = __floats2half2_rn(x0.z, x0.w);
    h[2] = __floats2half2_rn(x1.x, x1.y); h[3] = __floats2half2_rn(x1.z, x1.w);
    h[4] = __floats2half2_rn(x2.x, x2.y); h[5] = __floats2half2_rn(x2.z, x2.w);
    h[6] = __floats2half2_rn(x3.x, x3.y); h[7] = __floats2half2_rn(x3.z, x3.w);
    float4* dst = (float4*)(g_Ah + (size_t)m * KTOT + ki * HID + c);
    dst[0] = *(float4*)&h[0];
    dst[1] = *(float4*)&h[4];
}

// ─── prep: transpose W[4096,1024] -> [1024,4096] K-major fp16 ───────────────
__global__ void convert_W_kernel(const float* __restrict__ Wm) {
    __shared__ float tile[32][33];
    const int k0 = blockIdx.x * 32, n0 = blockIdx.y * 32;
    const int tx = threadIdx.x, ty = threadIdx.y;
    #pragma unroll
    for (int i = 0; i < 4; i++)
        tile[ty + i * 8][tx] = Wm[(size_t)(k0 + ty + i * 8) * HID + n0 + tx];
    __syncthreads();
    #pragma unroll
    for (int i = 0; i < 4; i++) {
        const float x = tile[tx][ty + i * 8];
        g_Bh[(size_t)(n0 + ty + i * 8) * KTOT + k0 + tx] = __float2half_rn(x);
    }
}

// ─── PTX helpers ────────────────────────────────────────────────────────────
__device__ __forceinline__ uint32_t smem_u32(const void* p) {
    uint32_t a;
    asm("{ .reg .u64 t; cvta.to.shared.u64 t, %1; cvt.u32.u64 %0, t; }" : "=r"(a) : "l"(p));
    return a;
}
__device__ __forceinline__ void cp16(uint32_t dst, const void* src) {
    asm volatile("cp.async.cg.shared.global [%0], [%1], 16;" :: "r"(dst), "l"(src));
}
__device__ __forceinline__ void ldsm_x4(uint32_t* r, uint32_t addr) {
    asm volatile("ldmatrix.sync.aligned.m8n8.x4.shared.b16 {%0,%1,%2,%3}, [%4];"
        : "=r"(r[0]), "=r"(r[1]), "=r"(r[2]), "=r"(r[3]) : "r"(addr));
}
__device__ __forceinline__ void mma_f16(float* c, const uint32_t* a, const uint32_t* b) {
    asm volatile("mma.sync.aligned.m16n8k16.row.col.f32.f16.f16.f32 "
        "{%0,%1,%2,%3}, {%4,%5,%6,%7}, {%8,%9}, {%0,%1,%2,%3};"
        : "+f"(c[0]), "+f"(c[1]), "+f"(c[2]), "+f"(c[3])
        : "r"(a[0]), "r"(a[1]), "r"(a[2]), "r"(a[3]), "r"(b[0]), "r"(b[1]));
}

// ─── main GEMM: 128x256 CTA, 8 warps (64x64), BK=64, 4-stage, 1 bar/iter ────
__global__ __launch_bounds__(256, 1) void gemm1x_kernel(float* __restrict__ out, int M) {
    extern __shared__ __align__(128) char smem[];
    const uint32_t sb = smem_u32(smem);
    const int tid  = threadIdx.x;
    const int lane = tid & 31;
    const int wid  = tid >> 5;
    const int wm   = wid & 1;          // 2 warps in M (64 rows)
    const int wn   = wid >> 1;         // 4 warps in N (64 cols)

    const int m0 = blockIdx.y * BM;
    const int n0 = blockIdx.x * BN;

    // cp.async mapping. A: 128 rows x 8 segs = 1024 segs (4/thread);
    //                   B: 256 rows x 8 segs = 2048 segs (8/thread).
    int a_row[4], a_col[4]; uint32_t a_dst[4]; int gra[4];
    #pragma unroll
    for (int j = 0; j < 4; j++) {
        const int s = tid + 256 * j;
        a_row[j] = s >> 3;  a_col[j] = s & 7;
        a_dst[j] = a_row[j] * 128 + ((a_col[j] ^ (a_row[j] & 7)) << 4);
        gra[j]   = min(m0 + a_row[j], M - 1);
    }
    int b_row[8], b_col[8]; uint32_t b_dst[8]; int grb[8];
    #pragma unroll
    for (int j = 0; j < 8; j++) {
        const int s = tid + 256 * j;
        b_row[j] = s >> 3;  b_col[j] = s & 7;
        b_dst[j] = b_row[j] * 128 + ((b_col[j] ^ (b_row[j] & 7)) << 4);
        grb[j]   = n0 + b_row[j];
    }

    float acc[4][8][4];
    #pragma unroll
    for (int i = 0; i < 4; i++)
        #pragma unroll
        for (int j = 0; j < 8; j++)
            #pragma unroll
            for (int q = 0; q < 4; q++) acc[i][j][q] = 0.0f;

    // ldmatrix lane-constant pieces (row offsets are multiples of 8)
    const int arow = wm * 64 + (lane & 15);
    const int asel = lane >> 4;
    const int aswz = arow & 7;
    const int brow = wn * 64 + ((lane >> 4) & 1) * 8 + (lane & 7);
    const int bsel = (lane >> 3) & 1;
    const int bswz = brow & 7;

    auto cp_chunk = [&](int c, int st) {
        const uint32_t base = sb + st * STAGE_B;
        const int k0 = c * BK;
        #pragma unroll
        for (int j = 0; j < 4; j++)
            cp16(base + a_dst[j], g_Ah + (size_t)gra[j] * KTOT + k0 + a_col[j] * 8);
        #pragma unroll
        for (int j = 0; j < 8; j++)
            cp16(base + TILE_A + b_dst[j], g_Bh + (size_t)grb[j] * KTOT + k0 + b_col[j] * 8);
    };

    auto compute_chunk = [&](int st) {
        const uint32_t base = sb + st * STAGE_B;
        #pragma unroll
        for (int kk = 0; kk < 4; kk++) {
            uint32_t a[4][4], b[4][4];
            const uint32_t acol = (uint32_t)(((kk * 2 + asel) ^ aswz) << 4);
            const uint32_t bcol = (uint32_t)(((kk * 2 + bsel) ^ bswz) << 4);
            #pragma unroll
            for (int i = 0; i < 4; i++)
                ldsm_x4(a[i], base + (arow + i * 16) * 128 + acol);
            #pragma unroll
            for (int jj = 0; jj < 4; jj++)
                ldsm_x4(b[jj], base + TILE_A + (brow + jj * 16) * 128 + bcol);
            #pragma unroll
            for (int i = 0; i < 4; i++)
                #pragma unroll
                for (int j = 0; j < 8; j++)
                    mma_f16(acc[i][j], a[i], &b[j >> 1][(j & 1) * 2]);
        }
    };

    // 4-stage pipeline, one barrier per iteration, wait_group 2 slack.
    // cp(c+3) overwrites stage (c+3)%4 == (c-1)%4, last read by compute(c-1),
    // which every warp finished before this iteration's barrier.
    cp_chunk(0, 0);
    asm volatile("cp.async.commit_group;" ::: "memory");
    cp_chunk(1, 1);
    asm volatile("cp.async.commit_group;" ::: "memory");
    cp_chunk(2, 2);
    asm volatile("cp.async.commit_group;" ::: "memory");

    #pragma unroll 1
    for (int c = 0; c < NCHUNK; c++) {
        asm volatile("cp.async.wait_group 2;" ::: "memory");   // cp(c) resident
        __syncthreads();
        if (c + 3 < NCHUNK) cp_chunk(c + 3, (c + 3) & 3);
        asm volatile("cp.async.commit_group;" ::: "memory");   // may be empty
        compute_chunk(c & 3);
    }

    // epilogue
    const int g = lane >> 2, t = lane & 3;
    #pragma unroll
    for (int i = 0; i < 4; i++) {
        #pragma unroll
        for (int j = 0; j < 8; j++) {
            const int r  = m0 + wm * 64 + i * 16 + g;
            const int cc = n0 + wn * 64 + j * 8 + t * 2;
            if (r < M)
                *(float2*)(out + (size_t)r * HID + cc) =
                    make_float2(acc[i][j][0], acc[i][j][1]);
            if (r + 8 < M)
                *(float2*)(out + (size_t)(r + 8) * HID + cc) =
                    make_float2(acc[i][j][2], acc[i][j][3]);
        }
    }
}

// ─── host ───────────────────────────────────────────────────────────────────
extern "C" void kernel_launch(void* const* d_in, const int* in_sizes, int n_in,
                              void* d_out, int out_size) {
    const float* feat  = (const float*)d_in[0];
    const int*   sizes = (const int*)  d_in[1];
    const float* Wm    = (const float*)d_in[2];
    float* out = (float*)d_out;

    const int n_images = in_sizes[1] / 2;
    const int M        = out_size / HID;

    convert_A_kernel<<<M, 256>>>(feat, sizes, n_images);
    convert_W_kernel<<<dim3(KTOT / 32, HID / 32), dim3(32, 8)>>>(Wm);

    static bool attr_set = false;
    if (!attr_set) {
        cudaFuncSetAttribute(gemm1x_kernel,
                             cudaFuncAttributeMaxDynamicSharedMemorySize, SMEM_TOTAL);
        attr_set = true;
    }
    dim3 grid(HID / BN, (M + BM - 1) / BM);   // (4, 117): N fastest -> A shared in L2
    gemm1x_kernel<<<grid, 256, SMEM_TOTAL>>>(out, M);
}

// round 9
// speedup vs baseline: 1.1761x; 1.1761x over previous
#include <cuda_runtime.h>
#include <cuda_fp16.h>
#include <cstdint>

// out[M,1024] = merged[M,4096] @ W[4096,1024], fp32 via single-pass fp16 HMMA.
// merged row m = concat of 4 gathered rows of image_features (2x2 patch merge).
// R9: 128x128 CTA, 4 warps x (64x64 warp tile) -> R8's LDSM/MAC reduction,
// but at 2 CTAs/SM (R8's 1 CTA/SM exposed every barrier; this restores overlap).

#define PATCH 14
#define HID   1024
#define KTOT  4096
#define MPAD  15104

#define BM 128
#define BN 128
#define BK 64                       // 64 halves = 128 B row: natural swizzle atom
#define NCHUNK (KTOT / BK)          // 64
#define TILE_SZ (128 * 128)         // 16384 B per operand tile
#define STAGE_B (2 * TILE_SZ)       // 32768 : Ah | Bh
#define NSTAGE 3
#define SMEM_TOTAL (NSTAGE * STAGE_B)   // 98304 -> 2 CTAs/SM

// scratch (static device memory — no runtime allocation)
__device__ __align__(128) __half g_Ah[(size_t)MPAD * KTOT];
__device__ __align__(128) __half g_Bh[(size_t)HID * KTOT];

// ─── prep: gather + fp32 -> fp16 into merged [M,4096] layout ────────────────
__global__ void convert_A_kernel(const float* __restrict__ feat,
                                 const int* __restrict__ sizes, int n_images) {
    __shared__ int s_src[4];
    const int m = blockIdx.x;
    const int tid = threadIdx.x;
    if (tid < 4) {
        int toff = 0, moff = 0, src = 0;
        for (int i = 0; i < n_images; i++) {
            const int h = sizes[2 * i] / PATCH, w = sizes[2 * i + 1] / PATCH;
            const int w2 = w >> 1, mr = (h >> 1) * w2;
            if (m < moff + mr) {
                const int r = m - moff;
                const int gr = r / w2, gc = r - gr * w2;
                src = toff + (2 * gr + (tid >> 1)) * w + 2 * gc + (tid & 1);
                break;
            }
            toff += h * w; moff += mr;
        }
        s_src[tid] = src;
    }
    __syncthreads();
    const int ki = tid >> 6;
    const int c  = (tid & 63) * 16;
    const float4* src = (const float4*)(feat + (size_t)s_src[ki] * HID + c);
    const float4 x0 = src[0], x1 = src[1], x2 = src[2], x3 = src[3];
    __half2 h[8];
    h[0] = __floats2half2_rn(x0.x, x0.y); h[1] = __floats2half2_rn(x0.z, x0.w);
    h[2] = __floats2half2_rn(x1.x, x1.y); h[3] = __floats2half2_rn(x1.z, x1.w);
    h[4] = __floats2half2_rn(x2.x, x2.y); h[5] = __floats2half2_rn(x2.z, x2.w);
    h[6] = __floats2half2_rn(x3.x, x3.y); h[7] = __floats2half2_rn(x3.z, x3.w);
    float4* dst = (float4*)(g_Ah + (size_t)m * KTOT + ki * HID + c);
    dst[0] = *(float4*)&h[0];
    dst[1] = *(float4*)&h[4];
}

// ─── prep: transpose W[4096,1024] -> [1024,4096] K-major fp16 ───────────────
__global__ void convert_W_kernel(const float* __restrict__ Wm) {
    __shared__ float tile[32][33];
    const int k0 = blockIdx.x * 32, n0 = blockIdx.y * 32;
    const int tx = threadIdx.x, ty = threadIdx.y;
    #pragma unroll
    for (int i = 0; i < 4; i++)
        tile[ty + i * 8][tx] = Wm[(size_t)(k0 + ty + i * 8) * HID + n0 + tx];
    __syncthreads();
    #pragma unroll
    for (int i = 0; i < 4; i++) {
        const float x = tile[tx][ty + i * 8];
        g_Bh[(size_t)(n0 + ty + i * 8) * KTOT + k0 + tx] = __float2half_rn(x);
    }
}

// ─── PTX helpers ────────────────────────────────────────────────────────────
__device__ __forceinline__ uint32_t smem_u32(const void* p) {
    uint32_t a;
    asm("{ .reg .u64 t; cvta.to.shared.u64 t, %1; cvt.u32.u64 %0, t; }" : "=r"(a) : "l"(p));
    return a;
}
__device__ __forceinline__ void cp16(uint32_t dst, const void* src) {
    asm volatile("cp.async.cg.shared.global [%0], [%1], 16;" :: "r"(dst), "l"(src));
}
__device__ __forceinline__ void ldsm_x4(uint32_t* r, uint32_t addr) {
    asm volatile("ldmatrix.sync.aligned.m8n8.x4.shared.b16 {%0,%1,%2,%3}, [%4];"
        : "=r"(r[0]), "=r"(r[1]), "=r"(r[2]), "=r"(r[3]) : "r"(addr));
}
__device__ __forceinline__ void mma_f16(float* c, const uint32_t* a, const uint32_t* b) {
    asm volatile("mma.sync.aligned.m16n8k16.row.col.f32.f16.f16.f32 "
        "{%0,%1,%2,%3}, {%4,%5,%6,%7}, {%8,%9}, {%0,%1,%2,%3};"
        : "+f"(c[0]), "+f"(c[1]), "+f"(c[2]), "+f"(c[3])
        : "r"(a[0]), "r"(a[1]), "r"(a[2]), "r"(a[3]), "r"(b[0]), "r"(b[1]));
}

// ─── main GEMM: 128x128 CTA, 4 warps (64x64), BK=64, 3-stage, 1 bar/iter ────
__global__ __launch_bounds__(128, 2) void gemm1x_kernel(float* __restrict__ out, int M) {
    extern __shared__ __align__(128) char smem[];
    const uint32_t sb = smem_u32(smem);
    const int tid  = threadIdx.x;
    const int lane = tid & 31;
    const int wid  = tid >> 5;
    const int wm   = wid & 1;          // 2 warps in M (64 rows)
    const int wn   = wid >> 1;         // 2 warps in N (64 cols)

    const int m0 = blockIdx.y * BM;
    const int n0 = blockIdx.x * BN;

    // cp.async mapping: each tile = 128 rows x 8 x 16B = 1024 segs; 8/thread
    int cp_row[8], cp_col[8]; uint32_t cp_dst[8]; int gra[8], grb[8];
    #pragma unroll
    for (int j = 0; j < 8; j++) {
        const int s = tid + 128 * j;
        cp_row[j] = s >> 3;  cp_col[j] = s & 7;
        cp_dst[j] = cp_row[j] * 128 + ((cp_col[j] ^ (cp_row[j] & 7)) << 4);
        gra[j]    = min(m0 + cp_row[j], M - 1);
        grb[j]    = n0 + cp_row[j];
    }

    float acc[4][8][4];
    #pragma unroll
    for (int i = 0; i < 4; i++)
        #pragma unroll
        for (int j = 0; j < 8; j++)
            #pragma unroll
            for (int q = 0; q < 4; q++) acc[i][j][q] = 0.0f;

    // ldmatrix lane-constant pieces (row offsets are multiples of 8)
    const int arow = wm * 64 + (lane & 15);
    const int asel = lane >> 4;
    const int aswz = arow & 7;
    const int brow = wn * 64 + ((lane >> 4) & 1) * 8 + (lane & 7);
    const int bsel = (lane >> 3) & 1;
    const int bswz = brow & 7;

    auto cp_chunk = [&](int c, int st) {
        const uint32_t base = sb + st * STAGE_B;
        const int k0 = c * BK;
        #pragma unroll
        for (int j = 0; j < 8; j++) {
            const int ko = k0 + cp_col[j] * 8;
            cp16(base + cp_dst[j],           g_Ah + (size_t)gra[j] * KTOT + ko);
            cp16(base + TILE_SZ + cp_dst[j], g_Bh + (size_t)grb[j] * KTOT + ko);
        }
    };

    auto compute_chunk = [&](int st) {
        const uint32_t base = sb + st * STAGE_B;
        #pragma unroll
        for (int kk = 0; kk < 4; kk++) {
            uint32_t a[4][4], b[4][4];
            const uint32_t acol = (uint32_t)(((kk * 2 + asel) ^ aswz) << 4);
            const uint32_t bcol = (uint32_t)(((kk * 2 + bsel) ^ bswz) << 4);
            #pragma unroll
            for (int i = 0; i < 4; i++)
                ldsm_x4(a[i], base + (arow + i * 16) * 128 + acol);
            #pragma unroll
            for (int jj = 0; jj < 4; jj++)
                ldsm_x4(b[jj], base + TILE_SZ + (brow + jj * 16) * 128 + bcol);
            #pragma unroll
            for (int i = 0; i < 4; i++)
                #pragma unroll
                for (int j = 0; j < 8; j++)
                    mma_f16(acc[i][j], a[i], &b[j >> 1][(j & 1) * 2]);
        }
    };

    // 3-stage pipeline, one barrier per iteration, wait_group 1 slack.
    // cp(c+2) overwrites stage (c+2)%3 == (c-1)%3, last read by compute(c-1),
    // which every warp finished before this iteration's barrier.
    cp_chunk(0, 0);
    asm volatile("cp.async.commit_group;" ::: "memory");
    cp_chunk(1, 1);
    asm volatile("cp.async.commit_group;" ::: "memory");

    int st_c = 0, st_p = 2;
    #pragma unroll 1
    for (int c = 0; c < NCHUNK; c++) {
        asm volatile("cp.async.wait_group 1;" ::: "memory");   // cp(c) resident
        __syncthreads();
        if (c + 2 < NCHUNK) cp_chunk(c + 2, st_p);
        asm volatile("cp.async.commit_group;" ::: "memory");   // may be empty
        compute_chunk(st_c);
        if (++st_c == NSTAGE) st_c = 0;
        if (++st_p == NSTAGE) st_p = 0;
    }

    // epilogue
    const int g = lane >> 2, t = lane & 3;
    #pragma unroll
    for (int i = 0; i < 4; i++) {
        #pragma unroll
        for (int j = 0; j < 8; j++) {
            const int r  = m0 + wm * 64 + i * 16 + g;
            const int cc = n0 + wn * 64 + j * 8 + t * 2;
            if (r < M)
                *(float2*)(out + (size_t)r * HID + cc) =
                    make_float2(acc[i][j][0], acc[i][j][1]);
            if (r + 8 < M)
                *(float2*)(out + (size_t)(r + 8) * HID + cc) =
                    make_float2(acc[i][j][2], acc[i][j][3]);
        }
    }
}

// ─── host ───────────────────────────────────────────────────────────────────
extern "C" void kernel_launch(void* const* d_in, const int* in_sizes, int n_in,
                              void* d_out, int out_size) {
    const float* feat  = (const float*)d_in[0];
    const int*   sizes = (const int*)  d_in[1];
    const float* Wm    = (const float*)d_in[2];
    float* out = (float*)d_out;

    const int n_images = in_sizes[1] / 2;
    const int M        = out_size / HID;

    convert_A_kernel<<<M, 256>>>(feat, sizes, n_images);
    convert_W_kernel<<<dim3(KTOT / 32, HID / 32), dim3(32, 8)>>>(Wm);

    static bool attr_set = false;
    if (!attr_set) {
        cudaFuncSetAttribute(gemm1x_kernel,
                             cudaFuncAttributeMaxDynamicSharedMemorySize, SMEM_TOTAL);
        attr_set = true;
    }
    dim3 grid(HID / BN, (M + BM - 1) / BM);   // (8, 117): N fastest -> A shared in L2
    gemm1x_kernel<<<grid, 128, SMEM_TOTAL>>>(out, M);
}

// round 10
// speedup vs baseline: 1.3397x; 1.1391x over previous
#include <cuda_runtime.h>
#include <cuda.h>
#include <cuda_fp16.h>
#include <cstdint>

// out[M,1024] = merged[M,4096] @ W[4096,1024], fp32 via single-pass fp16 HMMA.
// R10: R7 compute (64x32 warp tiles, 8 warps, 128x128 CTA, BK=64) but the
// cp.async + __syncthreads pipeline is replaced by TMA (cp.async.bulk.tensor,
// plain sm_103-legal) + mbarrier full/done pairs: no CTA-wide barrier in the
// mainloop, warps run decoupled; STS crossbar + LDGSTS issue removed.

#define PATCH 14
#define HID   1024
#define KTOT  4096
#define MPAD  15104

#define BM 128
#define BN 128
#define BK 64
#define NCHUNK (KTOT / BK)          // 64
#define TILE_SZ 16384               // 128 rows x 128 B (SW128)
#define STAGE_B (2 * TILE_SZ)       // 32768 : Ah | Bh
#define NSTAGE 3
#define SMEM_DATA 1024
#define SMEM_TOTAL (SMEM_DATA + NSTAGE * STAGE_B)   // 99328 -> 2 CTAs/SM

// mbarrier smem offsets: full[s] = s*8 (s=0..2), done[s] = 24 + s*8
#define OFF_FULL(s) ((s) * 8)
#define OFF_DONE(s) (24 + (s) * 8)

// scratch (static device memory — no runtime allocation)
__device__ __align__(128) __half g_Ah[(size_t)MPAD * KTOT];
__device__ __align__(128) __half g_Bh[(size_t)HID * KTOT];

// ─── PTX helpers (TMA/mbarrier subset verified to compile on sm_103 in R2) ──
__device__ __forceinline__ uint32_t smem_u32(const void* p) {
    uint32_t a;
    asm("{ .reg .u64 t; cvta.to.shared.u64 t, %1; cvt.u32.u64 %0, t; }" : "=r"(a) : "l"(p));
    return a;
}
#define MBAR_INIT(addr, cnt) \
    asm volatile("mbarrier.init.shared.b64 [%0], %1;" :: "r"(addr), "r"(cnt) : "memory")
#define MBAR_EXPECT_TX(addr, bytes) \
    asm volatile("mbarrier.arrive.expect_tx.shared.b64 _, [%0], %1;" :: "r"(addr), "r"(bytes) : "memory")
#define MBAR_ARRIVE(addr) \
    asm volatile("mbarrier.arrive.shared.b64 _, [%0];" :: "r"(addr) : "memory")
#define MBAR_WAIT(addr, parity) do {                                          \
    uint32_t _m = (addr), _p = (parity), _d;                                  \
    asm volatile("{\n\t.reg .pred p;\n\t"                                     \
        "mbarrier.try_wait.parity.acquire.cta.shared::cta.b64 p, [%1], %2;\n\t" \
        "selp.b32 %0, 1, 0, p;\n\t}"                                          \
        : "=r"(_d) : "r"(_m), "r"(_p) : "memory");                            \
    if (!_d) {                                                                \
        asm volatile("{\n\t.reg .pred P1;\n\t"                                \
            "WL_%=:\n\t"                                                      \
            "mbarrier.try_wait.parity.acquire.cta.shared::cta.b64 P1, [%0], %1, 0x989680;\n\t" \
            "@P1 bra.uni WD_%=;\n\t"                                          \
            "bra.uni WL_%=;\n\t"                                              \
            "WD_%=:\n\t}" :: "r"(_m), "r"(_p) : "memory");                    \
    }                                                                         \
} while (0)

__device__ __forceinline__ void tma_load_2d(uint32_t smem, const void* map,
                                            int cx, int cy, uint32_t mbar) {
    asm volatile(
        "cp.async.bulk.tensor.2d.shared::cta.global.tile.mbarrier::complete_tx::bytes "
        "[%0], [%1, {%2, %3}], [%4];"
        :: "r"(smem), "l"(map), "r"(cx), "r"(cy), "r"(mbar) : "memory");
}
__device__ __forceinline__ void ldsm_x4(uint32_t* r, uint32_t addr) {
    asm volatile("ldmatrix.sync.aligned.m8n8.x4.shared.b16 {%0,%1,%2,%3}, [%4];"
        : "=r"(r[0]), "=r"(r[1]), "=r"(r[2]), "=r"(r[3]) : "r"(addr));
}
__device__ __forceinline__ void mma_f16(float* c, const uint32_t* a, const uint32_t* b) {
    asm volatile("mma.sync.aligned.m16n8k16.row.col.f32.f16.f16.f32 "
        "{%0,%1,%2,%3}, {%4,%5,%6,%7}, {%8,%9}, {%0,%1,%2,%3};"
        : "+f"(c[0]), "+f"(c[1]), "+f"(c[2]), "+f"(c[3])
        : "r"(a[0]), "r"(a[1]), "r"(a[2]), "r"(a[3]), "r"(b[0]), "r"(b[1]));
}

// ─── prep: merged A-gather (fp32->fp16) and W-transpose in ONE kernel ───────
__global__ void convert_AW_kernel(const float* __restrict__ feat,
                                  const float* __restrict__ Wm,
                                  const int* __restrict__ sizes,
                                  int n_images, int M) {
    __shared__ int   s_src[4];
    __shared__ float tile[32][33];
    const int bx  = blockIdx.x;
    const int tid = threadIdx.x;
    if (bx < M) {
        // A part: one block per merged row
        if (tid < 4) {
            int toff = 0, moff = 0, src = 0;
            for (int i = 0; i < n_images; i++) {
                const int h = sizes[2 * i] / PATCH, w = sizes[2 * i + 1] / PATCH;
                const int w2 = w >> 1, mr = (h >> 1) * w2;
                if (bx < moff + mr) {
                    const int r = bx - moff;
                    const int gr = r / w2, gc = r - gr * w2;
                    src = toff + (2 * gr + (tid >> 1)) * w + 2 * gc + (tid & 1);
                    break;
                }
                toff += h * w; moff += mr;
            }
            s_src[tid] = src;
        }
        __syncthreads();
        const int ki = tid >> 6;
        const int c  = (tid & 63) * 16;
        const float4* src = (const float4*)(feat + (size_t)s_src[ki] * HID + c);
        const float4 x0 = src[0], x1 = src[1], x2 = src[2], x3 = src[3];
        __half2 h[8];
        h[0] = __floats2half2_rn(x0.x, x0.y); h[1] = __floats2half2_rn(x0.z, x0.w);
        h[2] = __floats2half2_rn(x1.x, x1.y); h[3] = __floats2half2_rn(x1.z, x1.w);
        h[4] = __floats2half2_rn(x2.x, x2.y); h[5] = __floats2half2_rn(x2.z, x2.w);
        h[6] = __floats2half2_rn(x3.x, x3.y); h[7] = __floats2half2_rn(x3.z, x3.w);
        float4* dst = (float4*)(g_Ah + (size_t)bx * KTOT + ki * HID + c);
        dst[0] = *(float4*)&h[0];
        dst[1] = *(float4*)&h[4];
    } else {
        // W part: 4096 blocks, each transposes a 32x32 tile
        const int b  = bx - M;
        const int k0 = (b & 127) * 32, n0 = (b >> 7) * 32;
        const int tx = tid & 31, ty = tid >> 5;     // 32 x 8
        #pragma unroll
        for (int i = 0; i < 4; i++)
            tile[ty + i * 8][tx] = Wm[(size_t)(k0 + ty + i * 8) * HID + n0 + tx];
        __syncthreads();
        #pragma unroll
        for (int i = 0; i < 4; i++) {
            const float x = tile[tx][ty + i * 8];
            g_Bh[(size_t)(n0 + ty + i * 8) * KTOT + k0 + tx] = __float2half_rn(x);
        }
    }
}

// ─── main GEMM: TMA + mbarrier pipeline, no CTA barriers in the loop ────────
__global__ __launch_bounds__(256, 2) void gemm_tma_kernel(
    const __grid_constant__ CUtensorMap tmA,
    const __grid_constant__ CUtensorMap tmB,
    float* __restrict__ out, int M)
{
    extern __shared__ __align__(1024) char smem[];
    const uint32_t sb = smem_u32(smem);
    const int tid  = threadIdx.x;
    const int lane = tid & 31;
    const int wid  = tid >> 5;
    const int wm   = wid & 1;          // 2 warps in M (64 rows)
    const int wn   = wid >> 1;         // 4 warps in N (32 cols)

    const int m0 = blockIdx.y * BM;
    const int n0 = blockIdx.x * BN;

    if (tid == 0) {
        #pragma unroll
        for (int s = 0; s < NSTAGE; s++) {
            MBAR_INIT(sb + OFF_FULL(s), 1);   // completed by TMA tx bytes
            MBAR_INIT(sb + OFF_DONE(s), 8);   // one arrive per warp
        }
    }
    __syncthreads();

    // prologue: produce chunks 0 and 1
    if (tid == 0) {
        #pragma unroll
        for (int pc = 0; pc < 2; pc++) {
            const uint32_t st = sb + SMEM_DATA + pc * STAGE_B;
            MBAR_EXPECT_TX(sb + OFF_FULL(pc), STAGE_B);
            tma_load_2d(st,           &tmA, pc * BK, m0, sb + OFF_FULL(pc));
            tma_load_2d(st + TILE_SZ, &tmB, pc * BK, n0, sb + OFF_FULL(pc));
        }
    }

    float acc[4][4][4];
    #pragma unroll
    for (int i = 0; i < 4; i++)
        #pragma unroll
        for (int j = 0; j < 4; j++)
            #pragma unroll
            for (int q = 0; q < 4; q++) acc[i][j][q] = 0.0f;

    // ldmatrix lane-constant pieces (same swizzle as TMA SW128)
    const int arow = wm * 64 + (lane & 15);
    const int asel = lane >> 4;
    const int aswz = arow & 7;
    const int brow = wn * 32 + ((lane >> 4) & 1) * 8 + (lane & 7);
    const int bsel = (lane >> 3) & 1;
    const int bswz = brow & 7;

    int cst = 0, cph = 0;              // consumer cursor
    int pst = 2, puse = 0;             // producer cursor (next chunk = c+2)

    #pragma unroll 1
    for (int c = 0; c < NCHUNK; c++) {
        // producer: thread 0 issues chunk c+2 into stage pst
        if (tid == 0 && c + 2 < NCHUNK) {
            const int pc = c + 2;
            if (pc >= NSTAGE)
                MBAR_WAIT(sb + OFF_DONE(pst), (puse - 1) & 1);
            const uint32_t st = sb + SMEM_DATA + pst * STAGE_B;
            MBAR_EXPECT_TX(sb + OFF_FULL(pst), STAGE_B);
            tma_load_2d(st,           &tmA, pc * BK, m0, sb + OFF_FULL(pst));
            tma_load_2d(st + TILE_SZ, &tmB, pc * BK, n0, sb + OFF_FULL(pst));
        }
        if (tid == 0) { if (++pst == NSTAGE) { pst = 0; puse++; } }

        // consumer: wait chunk c, compute, signal stage free
        MBAR_WAIT(sb + OFF_FULL(cst), cph);
        {
            const uint32_t base = sb + SMEM_DATA + cst * STAGE_B;
            #pragma unroll
            for (int kk = 0; kk < 4; kk++) {
                uint32_t a[4][4], b[2][4];
                const uint32_t acol = (uint32_t)(((kk * 2 + asel) ^ aswz) << 4);
                const uint32_t bcol = (uint32_t)(((kk * 2 + bsel) ^ bswz) << 4);
                #pragma unroll
                for (int i = 0; i < 4; i++)
                    ldsm_x4(a[i], base + (arow + i * 16) * 128 + acol);
                #pragma unroll
                for (int jj = 0; jj < 2; jj++)
                    ldsm_x4(b[jj], base + TILE_SZ + (brow + jj * 16) * 128 + bcol);
                #pragma unroll
                for (int i = 0; i < 4; i++)
                    #pragma unroll
                    for (int j = 0; j < 4; j++)
                        mma_f16(acc[i][j], a[i], &b[j >> 1][(j & 1) * 2]);
            }
        }
        if (lane == 0) MBAR_ARRIVE(sb + OFF_DONE(cst));
        if (++cst == NSTAGE) { cst = 0; cph ^= 1; }
    }

    // epilogue (each warp owns its acc; no further smem use)
    const int g = lane >> 2, t = lane & 3;
    #pragma unroll
    for (int i = 0; i < 4; i++) {
        #pragma unroll
        for (int j = 0; j < 4; j++) {
            const int r  = m0 + wm * 64 + i * 16 + g;
            const int cc = n0 + wn * 32 + j * 8 + t * 2;
            if (r < M)
                *(float2*)(out + (size_t)r * HID + cc) =
                    make_float2(acc[i][j][0], acc[i][j][1]);
            if (r + 8 < M)
                *(float2*)(out + (size_t)(r + 8) * HID + cc) =
                    make_float2(acc[i][j][2], acc[i][j][3]);
        }
    }
}

// ─── host ───────────────────────────────────────────────────────────────────
typedef CUresult (*PFN_encodeTiled)(
    CUtensorMap*, CUtensorMapDataType, cuuint32_t, void*,
    const cuuint64_t*, const cuuint64_t*, const cuuint32_t*, const cuuint32_t*,
    CUtensorMapInterleave, CUtensorMapSwizzle, CUtensorMapL2promotion,
    CUtensorMapFloatOOBfill);

static void make_map(PFN_encodeTiled fn, CUtensorMap* tm, void* ptr,
                     uint64_t d0, uint64_t d1, uint32_t b0, uint32_t b1) {
    cuuint64_t dims[2] = {d0, d1};
    cuuint64_t strides[1] = {d0 * sizeof(__half)};
    cuuint32_t box[2] = {b0, b1};
    cuuint32_t es[2] = {1, 1};
    fn(tm, CU_TENSOR_MAP_DATA_TYPE_FLOAT16, 2, ptr, dims, strides, box, es,
       CU_TENSOR_MAP_INTERLEAVE_NONE, CU_TENSOR_MAP_SWIZZLE_128B,
       CU_TENSOR_MAP_L2_PROMOTION_L2_128B, CU_TENSOR_MAP_FLOAT_OOB_FILL_NONE);
}

extern "C" void kernel_launch(void* const* d_in, const int* in_sizes, int n_in,
                              void* d_out, int out_size) {
    const float* feat  = (const float*)d_in[0];
    const int*   sizes = (const int*)  d_in[1];
    const float* Wm    = (const float*)d_in[2];
    float* out = (float*)d_out;

    const int n_images = in_sizes[1] / 2;
    const int M        = out_size / HID;

    convert_AW_kernel<<<M + (KTOT / 32) * (HID / 32), 256>>>(feat, Wm, sizes, n_images, M);

    static bool init_done = false;
    static CUtensorMap tmA, tmB;
    if (!init_done) {
        PFN_encodeTiled encode = nullptr;
        cudaDriverEntryPointQueryResult qr;
        cudaGetDriverEntryPointByVersion("cuTensorMapEncodeTiled", (void**)&encode,
                                         12000, cudaEnableDefault, &qr);
        void *pA, *pB;
        cudaGetSymbolAddress(&pA, g_Ah);
        cudaGetSymbolAddress(&pB, g_Bh);
        make_map(encode, &tmA, pA, KTOT, MPAD, BK, BM);
        make_map(encode, &tmB, pB, KTOT, HID,  BK, BN);
        cudaFuncSetAttribute(gemm_tma_kernel,
                             cudaFuncAttributeMaxDynamicSharedMemorySize, SMEM_TOTAL);
        init_done = true;
    }
    dim3 grid(HID / BN, (M + BM - 1) / BM);   // (8, 117): N fastest -> A shared in L2
    gemm_tma_kernel<<<grid, 256, SMEM_TOTAL>>>(tmA, tmB, out, M);
}

// round 12
// speedup vs baseline: 1.3408x; 1.0008x over previous
#include <cuda_runtime.h>
#include <cuda.h>
#include <cuda_fp16.h>
#include <cstdint>

// out[M,1024] = merged[M,4096] @ W[4096,1024], fp32 via single-pass fp16 HMMA.
// R12: TMA loads (no STS/LDGSTS), but stage recycling via ONE __syncthreads per
// iteration instead of done-mbarriers (R10/R11's protocol showed silent
// corruption: rel_err deviated from the bit-exact 2.934442e-4 of the cp.async
// versions). 64x128 CTA, 4 warps (32x64), 3 CTAs/SM, 1872 jobs (low quantization).

#define PATCH 14
#define HID   1024
#define KTOT  4096
#define MPAD  15104

#define BM 64
#define BN 128
#define BK 64
#define NCHUNK (KTOT / BK)          // 64
#define TILE_A  8192                // 64 rows x 128 B (SW128)
#define TILE_BB 16384               // 128 rows x 128 B
#define STAGE_B (TILE_A + TILE_BB)  // 24576
#define NSTAGE 3
#define SMEM_DATA 1024
#define SMEM_TOTAL (SMEM_DATA + NSTAGE * STAGE_B)   // 74752 -> 3 CTAs/SM

#define OFF_FULL(s) ((s) * 8)

// scratch (static device memory — no runtime allocation)
__device__ __align__(128) __half g_Ah[(size_t)MPAD * KTOT];
__device__ __align__(128) __half g_Bh[(size_t)HID * KTOT];

// ─── PTX helpers ────────────────────────────────────────────────────────────
__device__ __forceinline__ uint32_t smem_u32(const void* p) {
    uint32_t a;
    asm("{ .reg .u64 t; cvta.to.shared.u64 t, %1; cvt.u32.u64 %0, t; }" : "=r"(a) : "l"(p));
    return a;
}
#define MBAR_INIT(addr, cnt) \
    asm volatile("mbarrier.init.shared.b64 [%0], %1;" :: "r"(addr), "r"(cnt) : "memory")
#define MBAR_EXPECT_TX(addr, bytes) \
    asm volatile("mbarrier.arrive.expect_tx.shared.b64 _, [%0], %1;" :: "r"(addr), "r"(bytes) : "memory")
#define MBAR_WAIT(addr, parity) do {                                          \
    uint32_t _m = (addr), _p = (parity), _d;                                  \
    asm volatile("{\n\t.reg .pred p;\n\t"                                     \
        "mbarrier.try_wait.parity.acquire.cta.shared::cta.b64 p, [%1], %2;\n\t" \
        "selp.b32 %0, 1, 0, p;\n\t}"                                          \
        : "=r"(_d) : "r"(_m), "r"(_p) : "memory");                            \
    if (!_d) {                                                                \
        asm volatile("{\n\t.reg .pred P1;\n\t"                                \
            "WL_%=:\n\t"                                                      \
            "mbarrier.try_wait.parity.acquire.cta.shared::cta.b64 P1, [%0], %1, 0x989680;\n\t" \
            "@P1 bra.uni WD_%=;\n\t"                                          \
            "bra.uni WL_%=;\n\t"                                              \
            "WD_%=:\n\t}" :: "r"(_m), "r"(_p) : "memory");                    \
    }                                                                         \
} while (0)

__device__ __forceinline__ void tma_load_2d(uint32_t smem, const void* map,
                                            int cx, int cy, uint32_t mbar) {
    asm volatile(
        "cp.async.bulk.tensor.2d.shared::cta.global.tile.mbarrier::complete_tx::bytes "
        "[%0], [%1, {%2, %3}], [%4];"
        :: "r"(smem), "l"(map), "r"(cx), "r"(cy), "r"(mbar) : "memory");
}
__device__ __forceinline__ void ldsm_x4(uint32_t* r, uint32_t addr) {
    asm volatile("ldmatrix.sync.aligned.m8n8.x4.shared.b16 {%0,%1,%2,%3}, [%4];"
        : "=r"(r[0]), "=r"(r[1]), "=r"(r[2]), "=r"(r[3]) : "r"(addr));
}
__device__ __forceinline__ void mma_f16(float* c, const uint32_t* a, const uint32_t* b) {
    asm volatile("mma.sync.aligned.m16n8k16.row.col.f32.f16.f16.f32 "
        "{%0,%1,%2,%3}, {%4,%5,%6,%7}, {%8,%9}, {%0,%1,%2,%3};"
        : "+f"(c[0]), "+f"(c[1]), "+f"(c[2]), "+f"(c[3])
        : "r"(a[0]), "r"(a[1]), "r"(a[2]), "r"(a[3]), "r"(b[0]), "r"(b[1]));
}

// ─── prep: A gather/convert + pad-row zeroing + W transpose, one launch ─────
__global__ void convert_AW_kernel(const float* __restrict__ feat,
                                  const float* __restrict__ Wm,
                                  const int* __restrict__ sizes,
                                  int n_images, int M, int n_pad) {
    __shared__ int   s_src[4];
    __shared__ float tile[32][33];
    const int bx  = blockIdx.x;
    const int tid = threadIdx.x;
    if (bx < M) {
        if (tid < 4) {
            int toff = 0, moff = 0, src = 0;
            for (int i = 0; i < n_images; i++) {
                const int h = sizes[2 * i] / PATCH, w = sizes[2 * i + 1] / PATCH;
                const int w2 = w >> 1, mr = (h >> 1) * w2;
                if (bx < moff + mr) {
                    const int r = bx - moff;
                    const int gr = r / w2, gc = r - gr * w2;
                    src = toff + (2 * gr + (tid >> 1)) * w + 2 * gc + (tid & 1);
                    break;
                }
                toff += h * w; moff += mr;
            }
            s_src[tid] = src;
        }
        __syncthreads();
        const int ki = tid >> 6;
        const int c  = (tid & 63) * 16;
        const float4* src = (const float4*)(feat + (size_t)s_src[ki] * HID + c);
        const float4 x0 = src[0], x1 = src[1], x2 = src[2], x3 = src[3];
        __half2 h[8];
        h[0] = __floats2half2_rn(x0.x, x0.y); h[1] = __floats2half2_rn(x0.z, x0.w);
        h[2] = __floats2half2_rn(x1.x, x1.y); h[3] = __floats2half2_rn(x1.z, x1.w);
        h[4] = __floats2half2_rn(x2.x, x2.y); h[5] = __floats2half2_rn(x2.z, x2.w);
        h[6] = __floats2half2_rn(x3.x, x3.y); h[7] = __floats2half2_rn(x3.z, x3.w);
        float4* dst = (float4*)(g_Ah + (size_t)bx * KTOT + ki * HID + c);
        dst[0] = *(float4*)&h[0];
        dst[1] = *(float4*)&h[4];
    } else if (bx < M + n_pad) {
        float4* dst = (float4*)(g_Ah + (size_t)bx * KTOT) + tid * 2;
        dst[0] = make_float4(0.f, 0.f, 0.f, 0.f);
        dst[1] = make_float4(0.f, 0.f, 0.f, 0.f);
    } else {
        const int b  = bx - M - n_pad;
        const int k0 = (b & 127) * 32, n0 = (b >> 7) * 32;
        const int tx = tid & 31, ty = tid >> 5;
        #pragma unroll
        for (int i = 0; i < 4; i++)
            tile[ty + i * 8][tx] = Wm[(size_t)(k0 + ty + i * 8) * HID + n0 + tx];
        __syncthreads();
        #pragma unroll
        for (int i = 0; i < 4; i++) {
            const float x = tile[tx][ty + i * 8];
            g_Bh[(size_t)(n0 + ty + i * 8) * KTOT + k0 + tx] = __float2half_rn(x);
        }
    }
}

// ─── main GEMM: 64x128 CTA, 4 warps (32x64), TMA + sync-recycled stages ─────
__global__ __launch_bounds__(128, 3) void gemm_tma_kernel(
    const __grid_constant__ CUtensorMap tmA,
    const __grid_constant__ CUtensorMap tmB,
    float* __restrict__ out, int M)
{
    extern __shared__ __align__(1024) char smem[];
    const uint32_t sb = smem_u32(smem);
    const int tid  = threadIdx.x;
    const int lane = tid & 31;
    const int wid  = tid >> 5;
    const int wm   = wid & 1;          // 2 warps in M (32 rows each)
    const int wn   = wid >> 1;         // 2 warps in N (64 cols each)

    const int m0 = blockIdx.y * BM;
    const int n0 = blockIdx.x * BN;

    if (tid == 0) {
        #pragma unroll
        for (int s = 0; s < NSTAGE; s++)
            MBAR_INIT(sb + OFF_FULL(s), 1);
    }
    __syncthreads();

    // prologue: chunks 0 and 1
    if (tid == 0) {
        #pragma unroll
        for (int pc = 0; pc < 2; pc++) {
            const uint32_t st = sb + SMEM_DATA + pc * STAGE_B;
            MBAR_EXPECT_TX(sb + OFF_FULL(pc), STAGE_B);
            tma_load_2d(st,          &tmA, pc * BK, m0, sb + OFF_FULL(pc));
            tma_load_2d(st + TILE_A, &tmB, pc * BK, n0, sb + OFF_FULL(pc));
        }
    }

    float acc[2][8][4];
    #pragma unroll
    for (int i = 0; i < 2; i++)
        #pragma unroll
        for (int j = 0; j < 8; j++)
            #pragma unroll
            for (int q = 0; q < 4; q++) acc[i][j][q] = 0.0f;

    const int arow = wm * 32 + (lane & 15);
    const int asel = lane >> 4;
    const int aswz = arow & 7;
    const int brow = wn * 64 + ((lane >> 4) & 1) * 8 + (lane & 7);
    const int bsel = (lane >> 3) & 1;
    const int bswz = brow & 7;

    int cst = 0, cph = 0;

    #pragma unroll 1
    for (int c = 0; c < NCHUNK; c++) {
        // wait chunk c loaded
        MBAR_WAIT(sb + OFF_FULL(cst), cph);

        // compute chunk c
        {
            const uint32_t base = sb + SMEM_DATA + cst * STAGE_B;
            #pragma unroll
            for (int kk = 0; kk < 4; kk++) {
                uint32_t a[2][4], b[4][4];
                const uint32_t acol = (uint32_t)(((kk * 2 + asel) ^ aswz) << 4);
                const uint32_t bcol = (uint32_t)(((kk * 2 + bsel) ^ bswz) << 4);
                #pragma unroll
                for (int i = 0; i < 2; i++)
                    ldsm_x4(a[i], base + (arow + i * 16) * 128 + acol);
                #pragma unroll
                for (int jj = 0; jj < 4; jj++)
                    ldsm_x4(b[jj], base + TILE_A + (brow + jj * 16) * 128 + bcol);
                #pragma unroll
                for (int i = 0; i < 2; i++)
                    #pragma unroll
                    for (int j = 0; j < 8; j++)
                        mma_f16(acc[i][j], a[i], &b[j >> 1][(j & 1) * 2]);
            }
        }

        // all warps finished reading stage cst (and, transitively, stage
        // (c+2)%3 == (c-1)%3 at iter c). Recycle it for chunk c+2.
        __syncthreads();
        if (tid == 0 && c + 2 < NCHUNK) {
            const int pc = c + 2;
            const int ps = pc % NSTAGE;
            const uint32_t st = sb + SMEM_DATA + ps * STAGE_B;
            MBAR_EXPECT_TX(sb + OFF_FULL(ps), STAGE_B);
            tma_load_2d(st,          &tmA, pc * BK, m0, sb + OFF_FULL(ps));
            tma_load_2d(st + TILE_A, &tmB, pc * BK, n0, sb + OFF_FULL(ps));
        }
        if (++cst == NSTAGE) { cst = 0; cph ^= 1; }
    }

    // epilogue
    const int g = lane >> 2, t = lane & 3;
    #pragma unroll
    for (int i = 0; i < 2; i++) {
        #pragma unroll
        for (int j = 0; j < 8; j++) {
            const int r  = m0 + wm * 32 + i * 16 + g;
            const int cc = n0 + wn * 64 + j * 8 + t * 2;
            if (r < M)
                *(float2*)(out + (size_t)r * HID + cc) =
                    make_float2(acc[i][j][0], acc[i][j][1]);
            if (r + 8 < M)
                *(float2*)(out + (size_t)(r + 8) * HID + cc) =
                    make_float2(acc[i][j][2], acc[i][j][3]);
        }
    }
}

// ─── host ───────────────────────────────────────────────────────────────────
typedef CUresult (*PFN_encodeTiled)(
    CUtensorMap*, CUtensorMapDataType, cuuint32_t, void*,
    const cuuint64_t*, const cuuint64_t*, const cuuint32_t*, const cuuint32_t*,
    CUtensorMapInterleave, CUtensorMapSwizzle, CUtensorMapL2promotion,
    CUtensorMapFloatOOBfill);

static void make_map(PFN_encodeTiled fn, CUtensorMap* tm, void* ptr,
                     uint64_t d0, uint64_t d1, uint32_t b0, uint32_t b1) {
    cuuint64_t dims[2] = {d0, d1};
    cuuint64_t strides[1] = {d0 * sizeof(__half)};
    cuuint32_t box[2] = {b0, b1};
    cuuint32_t es[2] = {1, 1};
    fn(tm, CU_TENSOR_MAP_DATA_TYPE_FLOAT16, 2, ptr, dims, strides, box, es,
       CU_TENSOR_MAP_INTERLEAVE_NONE, CU_TENSOR_MAP_SWIZZLE_128B,
       CU_TENSOR_MAP_L2_PROMOTION_L2_128B, CU_TENSOR_MAP_FLOAT_OOB_FILL_NONE);
}

extern "C" void kernel_launch(void* const* d_in, const int* in_sizes, int n_in,
                              void* d_out, int out_size) {
    const float* feat  = (const float*)d_in[0];
    const int*   sizes = (const int*)  d_in[1];
    const float* Wm    = (const float*)d_in[2];
    float* out = (float*)d_out;

    const int n_images = in_sizes[1] / 2;
    const int M        = out_size / HID;
    const int n_pad    = MPAD - M;

    convert_AW_kernel<<<M + n_pad + (KTOT / 32) * (HID / 32), 256>>>(
        feat, Wm, sizes, n_images, M, n_pad);

    static bool init_done = false;
    static CUtensorMap tmA, tmB;
    if (!init_done) {
        PFN_encodeTiled encode = nullptr;
        cudaDriverEntryPointQueryResult qr;
        cudaGetDriverEntryPointByVersion("cuTensorMapEncodeTiled", (void**)&encode,
                                         12000, cudaEnableDefault, &qr);
        void *pA, *pB;
        cudaGetSymbolAddress(&pA, g_Ah);
        cudaGetSymbolAddress(&pB, g_Bh);
        make_map(encode, &tmA, pA, KTOT, MPAD, BK, BM);
        make_map(encode, &tmB, pB, KTOT, HID,  BK, BN);
        cudaFuncSetAttribute(gemm_tma_kernel,
                             cudaFuncAttributeMaxDynamicSharedMemorySize, SMEM_TOTAL);
        init_done = true;
    }
    dim3 grid(HID / BN, (M + BM - 1) / BM);   // (8, 234): N fastest -> A shared in L2
    gemm_tma_kernel<<<grid, 128, SMEM_TOTAL>>>(tmA, tmB, out, M);
}

// round 13
// speedup vs baseline: 1.3826x; 1.0312x over previous
#include <cuda_runtime.h>
#include <cuda.h>
#include <cuda_fp16.h>
#include <cstdint>

// out[M,1024] = merged[M,4096] @ W[4096,1024], fp32 via single-pass fp16 HMMA.
// R13: R12's verified TMA + sync-recycled pipeline made PERSISTENT: 444 CTAs
// (3/SM) pull tiles from an atomic counter; stage-ring cursors roll across
// tiles (linear mbarrier parity stream). Kills the 4.22-wave tail (~18%).

#define PATCH 14
#define HID   1024
#define KTOT  4096
#define MPAD  15104

#define BM 64
#define BN 128
#define BK 64
#define NCHUNK (KTOT / BK)          // 64
#define TILE_A  8192                // 64 rows x 128 B (SW128)
#define TILE_BB 16384               // 128 rows x 128 B
#define STAGE_B (TILE_A + TILE_BB)  // 24576
#define NSTAGE 3
#define SMEM_DATA 1024
#define SMEM_TOTAL (SMEM_DATA + NSTAGE * STAGE_B)   // 74752 -> 3 CTAs/SM

#define NCTAS 444                   // 148 SMs x 3

#define OFF_FULL(s) ((s) * 8)
#define OFF_TILE 64                 // smem slot for broadcast tile index

// scratch (static device memory — no runtime allocation)
__device__ __align__(128) __half g_Ah[(size_t)MPAD * KTOT];
__device__ __align__(128) __half g_Bh[(size_t)HID * KTOT];
__device__ int g_tile_ctr;

// ─── PTX helpers ────────────────────────────────────────────────────────────
__device__ __forceinline__ uint32_t smem_u32(const void* p) {
    uint32_t a;
    asm("{ .reg .u64 t; cvta.to.shared.u64 t, %1; cvt.u32.u64 %0, t; }" : "=r"(a) : "l"(p));
    return a;
}
#define MBAR_INIT(addr, cnt) \
    asm volatile("mbarrier.init.shared.b64 [%0], %1;" :: "r"(addr), "r"(cnt) : "memory")
#define MBAR_EXPECT_TX(addr, bytes) \
    asm volatile("mbarrier.arrive.expect_tx.shared.b64 _, [%0], %1;" :: "r"(addr), "r"(bytes) : "memory")
#define MBAR_WAIT(addr, parity) do {                                          \
    uint32_t _m = (addr), _p = (parity), _d;                                  \
    asm volatile("{\n\t.reg .pred p;\n\t"                                     \
        "mbarrier.try_wait.parity.acquire.cta.shared::cta.b64 p, [%1], %2;\n\t" \
        "selp.b32 %0, 1, 0, p;\n\t}"                                          \
        : "=r"(_d) : "r"(_m), "r"(_p) : "memory");                            \
    if (!_d) {                                                                \
        asm volatile("{\n\t.reg .pred P1;\n\t"                                \
            "WL_%=:\n\t"                                                      \
            "mbarrier.try_wait.parity.acquire.cta.shared::cta.b64 P1, [%0], %1, 0x989680;\n\t" \
            "@P1 bra.uni WD_%=;\n\t"                                          \
            "bra.uni WL_%=;\n\t"                                              \
            "WD_%=:\n\t}" :: "r"(_m), "r"(_p) : "memory");                    \
    }                                                                         \
} while (0)

__device__ __forceinline__ void tma_load_2d(uint32_t smem, const void* map,
                                            int cx, int cy, uint32_t mbar) {
    asm volatile(
        "cp.async.bulk.tensor.2d.shared::cta.global.tile.mbarrier::complete_tx::bytes "
        "[%0], [%1, {%2, %3}], [%4];"
        :: "r"(smem), "l"(map), "r"(cx), "r"(cy), "r"(mbar) : "memory");
}
__device__ __forceinline__ void ldsm_x4(uint32_t* r, uint32_t addr) {
    asm volatile("ldmatrix.sync.aligned.m8n8.x4.shared.b16 {%0,%1,%2,%3}, [%4];"
        : "=r"(r[0]), "=r"(r[1]), "=r"(r[2]), "=r"(r[3]) : "r"(addr));
}
__device__ __forceinline__ void mma_f16(float* c, const uint32_t* a, const uint32_t* b) {
    asm volatile("mma.sync.aligned.m16n8k16.row.col.f32.f16.f16.f32 "
        "{%0,%1,%2,%3}, {%4,%5,%6,%7}, {%8,%9}, {%0,%1,%2,%3};"
        : "+f"(c[0]), "+f"(c[1]), "+f"(c[2]), "+f"(c[3])
        : "r"(a[0]), "r"(a[1]), "r"(a[2]), "r"(a[3]), "r"(b[0]), "r"(b[1]));
}

// ─── prep: A gather/convert + pad zeroing + W transpose + counter reset ─────
__global__ void convert_AW_kernel(const float* __restrict__ feat,
                                  const float* __restrict__ Wm,
                                  const int* __restrict__ sizes,
                                  int n_images, int M, int n_pad) {
    __shared__ int   s_src[4];
    __shared__ float tile[32][33];
    const int bx  = blockIdx.x;
    const int tid = threadIdx.x;
    if (bx == 0 && tid == 0) g_tile_ctr = 0;   // reset work-steal counter
    if (bx < M) {
        if (tid < 4) {
            int toff = 0, moff = 0, src = 0;
            for (int i = 0; i < n_images; i++) {
                const int h = sizes[2 * i] / PATCH, w = sizes[2 * i + 1] / PATCH;
                const int w2 = w >> 1, mr = (h >> 1) * w2;
                if (bx < moff + mr) {
                    const int r = bx - moff;
                    const int gr = r / w2, gc = r - gr * w2;
                    src = toff + (2 * gr + (tid >> 1)) * w + 2 * gc + (tid & 1);
                    break;
                }
                toff += h * w; moff += mr;
            }
            s_src[tid] = src;
        }
        __syncthreads();
        const int ki = tid >> 6;
        const int c  = (tid & 63) * 16;
        const float4* src = (const float4*)(feat + (size_t)s_src[ki] * HID + c);
        const float4 x0 = src[0], x1 = src[1], x2 = src[2], x3 = src[3];
        __half2 h[8];
        h[0] = __floats2half2_rn(x0.x, x0.y); h[1] = __floats2half2_rn(x0.z, x0.w);
        h[2] = __floats2half2_rn(x1.x, x1.y); h[3] = __floats2half2_rn(x1.z, x1.w);
        h[4] = __floats2half2_rn(x2.x, x2.y); h[5] = __floats2half2_rn(x2.z, x2.w);
        h[6] = __floats2half2_rn(x3.x, x3.y); h[7] = __floats2half2_rn(x3.z, x3.w);
        float4* dst = (float4*)(g_Ah + (size_t)bx * KTOT + ki * HID + c);
        dst[0] = *(float4*)&h[0];
        dst[1] = *(float4*)&h[4];
    } else if (bx < M + n_pad) {
        float4* dst = (float4*)(g_Ah + (size_t)bx * KTOT) + tid * 2;
        dst[0] = make_float4(0.f, 0.f, 0.f, 0.f);
        dst[1] = make_float4(0.f, 0.f, 0.f, 0.f);
    } else {
        const int b  = bx - M - n_pad;
        const int k0 = (b & 127) * 32, n0 = (b >> 7) * 32;
        const int tx = tid & 31, ty = tid >> 5;
        #pragma unroll
        for (int i = 0; i < 4; i++)
            tile[ty + i * 8][tx] = Wm[(size_t)(k0 + ty + i * 8) * HID + n0 + tx];
        __syncthreads();
        #pragma unroll
        for (int i = 0; i < 4; i++) {
            const float x = tile[tx][ty + i * 8];
            g_Bh[(size_t)(n0 + ty + i * 8) * KTOT + k0 + tx] = __float2half_rn(x);
        }
    }
}

// ─── main GEMM: persistent, work-stealing, TMA + sync-recycled ring ─────────
__global__ __launch_bounds__(128, 3) void gemm_tma_kernel(
    const __grid_constant__ CUtensorMap tmA,
    const __grid_constant__ CUtensorMap tmB,
    float* __restrict__ out, int M, int ntiles)
{
    extern __shared__ __align__(1024) char smem[];
    const uint32_t sb = smem_u32(smem);
    const int tid  = threadIdx.x;
    const int lane = tid & 31;
    const int wid  = tid >> 5;
    const int wm   = wid & 1;
    const int wn   = wid >> 1;

    if (tid == 0) {
        #pragma unroll
        for (int s = 0; s < NSTAGE; s++)
            MBAR_INIT(sb + OFF_FULL(s), 1);
    }
    __syncthreads();

    const int arow = wm * 32 + (lane & 15);
    const int asel = lane >> 4;
    const int aswz = arow & 7;
    const int brow = wn * 64 + ((lane >> 4) & 1) * 8 + (lane & 7);
    const int bsel = (lane >> 3) & 1;
    const int bswz = brow & 7;
    const int g = lane >> 2, t4 = lane & 3;

    int cst = 0, cph = 0;   // ring cursor, rolls across tiles (linear parity)

    while (true) {
        // fetch next tile (deterministic output: each tile written once)
        if (tid == 0)
            *(volatile int*)(smem + OFF_TILE) = atomicAdd(&g_tile_ctr, 1);
        __syncthreads();
        const int t = *(volatile int*)(smem + OFF_TILE);
        __syncthreads();                    // smem slot safe for next round
        if (t >= ntiles) break;
        const int m0 = (t >> 3) * BM;
        const int n0 = (t & 7) * BN;

        // prologue: chunks 0,1 into ring slots cst, cst+1 (free: all prior
        // chunks consumed before we reached this point)
        if (tid == 0) {
            int ps = cst;
            #pragma unroll
            for (int pc = 0; pc < 2; pc++) {
                const uint32_t st = sb + SMEM_DATA + ps * STAGE_B;
                MBAR_EXPECT_TX(sb + OFF_FULL(ps), STAGE_B);
                tma_load_2d(st,          &tmA, pc * BK, m0, sb + OFF_FULL(ps));
                tma_load_2d(st + TILE_A, &tmB, pc * BK, n0, sb + OFF_FULL(ps));
                if (++ps == NSTAGE) ps = 0;
            }
        }

        float acc[2][8][4];
        #pragma unroll
        for (int i = 0; i < 2; i++)
            #pragma unroll
            for (int j = 0; j < 8; j++)
                #pragma unroll
                for (int q = 0; q < 4; q++) acc[i][j][q] = 0.0f;

        int pslot = (cst + 2) % NSTAGE;     // slot for chunk c+2

        #pragma unroll 1
        for (int c = 0; c < NCHUNK; c++) {
            MBAR_WAIT(sb + OFF_FULL(cst), cph);
            {
                const uint32_t base = sb + SMEM_DATA + cst * STAGE_B;
                #pragma unroll
                for (int kk = 0; kk < 4; kk++) {
                    uint32_t a[2][4], b[4][4];
                    const uint32_t acol = (uint32_t)(((kk * 2 + asel) ^ aswz) << 4);
                    const uint32_t bcol = (uint32_t)(((kk * 2 + bsel) ^ bswz) << 4);
                    #pragma unroll
                    for (int i = 0; i < 2; i++)
                        ldsm_x4(a[i], base + (arow + i * 16) * 128 + acol);
                    #pragma unroll
                    for (int jj = 0; jj < 4; jj++)
                        ldsm_x4(b[jj], base + TILE_A + (brow + jj * 16) * 128 + bcol);
                    #pragma unroll
                    for (int i = 0; i < 2; i++)
                        #pragma unroll
                        for (int j = 0; j < 8; j++)
                            mma_f16(acc[i][j], a[i], &b[j >> 1][(j & 1) * 2]);
                }
            }
            __syncthreads();                // stage pslot's old chunk consumed
            if (tid == 0 && c + 2 < NCHUNK) {
                const int pc = c + 2;
                const uint32_t st = sb + SMEM_DATA + pslot * STAGE_B;
                MBAR_EXPECT_TX(sb + OFF_FULL(pslot), STAGE_B);
                tma_load_2d(st,          &tmA, pc * BK, m0, sb + OFF_FULL(pslot));
                tma_load_2d(st + TILE_A, &tmB, pc * BK, n0, sb + OFF_FULL(pslot));
            }
            if (++pslot == NSTAGE) pslot = 0;
            if (++cst == NSTAGE) { cst = 0; cph ^= 1; }
        }

        // epilogue for this tile
        #pragma unroll
        for (int i = 0; i < 2; i++) {
            #pragma unroll
            for (int j = 0; j < 8; j++) {
                const int r  = m0 + wm * 32 + i * 16 + g;
                const int cc = n0 + wn * 64 + j * 8 + t4 * 2;
                if (r < M)
                    *(float2*)(out + (size_t)r * HID + cc) =
                        make_float2(acc[i][j][0], acc[i][j][1]);
                if (r + 8 < M)
                    *(float2*)(out + (size_t)(r + 8) * HID + cc) =
                        make_float2(acc[i][j][2], acc[i][j][3]);
            }
        }
    }
}

// ─── host ───────────────────────────────────────────────────────────────────
typedef CUresult (*PFN_encodeTiled)(
    CUtensorMap*, CUtensorMapDataType, cuuint32_t, void*,
    const cuuint64_t*, const cuuint64_t*, const cuuint32_t*, const cuuint32_t*,
    CUtensorMapInterleave, CUtensorMapSwizzle, CUtensorMapL2promotion,
    CUtensorMapFloatOOBfill);

static void make_map(PFN_encodeTiled fn, CUtensorMap* tm, void* ptr,
                     uint64_t d0, uint64_t d1, uint32_t b0, uint32_t b1) {
    cuuint64_t dims[2] = {d0, d1};
    cuuint64_t strides[1] = {d0 * sizeof(__half)};
    cuuint32_t box[2] = {b0, b1};
    cuuint32_t es[2] = {1, 1};
    fn(tm, CU_TENSOR_MAP_DATA_TYPE_FLOAT16, 2, ptr, dims, strides, box, es,
       CU_TENSOR_MAP_INTERLEAVE_NONE, CU_TENSOR_MAP_SWIZZLE_128B,
       CU_TENSOR_MAP_L2_PROMOTION_L2_128B, CU_TENSOR_MAP_FLOAT_OOB_FILL_NONE);
}

extern "C" void kernel_launch(void* const* d_in, const int* in_sizes, int n_in,
                              void* d_out, int out_size) {
    const float* feat  = (const float*)d_in[0];
    const int*   sizes = (const int*)  d_in[1];
    const float* Wm    = (const float*)d_in[2];
    float* out = (float*)d_out;

    const int n_images = in_sizes[1] / 2;
    const int M        = out_size / HID;
    const int n_pad    = MPAD - M;
    const int ntiles   = ((M + BM - 1) / BM) * (HID / BN);   // 234 * 8 = 1872

    convert_AW_kernel<<<M + n_pad + (KTOT / 32) * (HID / 32), 256>>>(
        feat, Wm, sizes, n_images, M, n_pad);

    static bool init_done = false;
    static CUtensorMap tmA, tmB;
    if (!init_done) {
        PFN_encodeTiled encode = nullptr;
        cudaDriverEntryPointQueryResult qr;
        cudaGetDriverEntryPointByVersion("cuTensorMapEncodeTiled", (void**)&encode,
                                         12000, cudaEnableDefault, &qr);
        void *pA, *pB;
        cudaGetSymbolAddress(&pA, g_Ah);
        cudaGetSymbolAddress(&pB, g_Bh);
        make_map(encode, &tmA, pA, KTOT, MPAD, BK, BM);
        make_map(encode, &tmB, pB, KTOT, HID,  BK, BN);
        cudaFuncSetAttribute(gemm_tma_kernel,
                             cudaFuncAttributeMaxDynamicSharedMemorySize, SMEM_TOTAL);
        init_done = true;
    }
    gemm_tma_kernel<<<NCTAS, 128, SMEM_TOTAL>>>(tmA, tmB, out, M, ntiles);
}